// round 13
// baseline (speedup 1.0000x reference)
#include <cuda_runtime.h>
#include <cuda_bf16.h>
#include <math.h>

#define Nn 60000
#define Dd 512
#define HH 245
#define NPOS 60025
#define NSEQ 60026
#define SST 60032
#define RT 5
#define NBLK7 632
#define CHUNK7 95
#define NENC 7500
#define INV_SQRT_D 0.04419417382415922f

// ---------------- scratch (device globals: allocation-free) ----------------
__device__ unsigned long long g_key = 0ull;   // reset at end of k_o_fc each call
__device__ float g_q[Dd];
__device__ float g_u[8 * Dd];
__device__ float g_c[8];
__device__ __nv_bfloat16 g_xxh[(size_t)NPOS * Dd];   // ~61 MB conv output (bf16)
__device__ float g_scores[8 * SST];
__device__ float g_mp[512 * 8];
__device__ float g_sp[512 * 8];
__device__ float g_m[8];
__device__ float g_rinv[8];
__device__ float g_spart[(size_t)NBLK7 * 4096];
__device__ float g_gp1[8 * Dd];            // gemv partials (q, then av)
__device__ float g_gp2[8 * Dd];            // gemv partials (o)

__device__ __forceinline__ int decode_idx(unsigned long long key) {
    return (int)(0xFFFFFFFFu - (unsigned)(key & 0xFFFFFFFFull));
}

// ---------------- K1: a1 = sigmoid(inputs@w_enc+b), A1 out, argmax via atomicMax ----------------
__global__ void k_enc(const float* __restrict__ inputs,
                      const float* __restrict__ w_enc,
                      const float* __restrict__ b_enc,
                      float* __restrict__ a1_out) {
    __shared__ float w_sh[Dd];
    __shared__ unsigned long long keys[8];
    int t = threadIdx.x;               // 256 threads, 8 warps
    w_sh[t] = w_enc[t];
    w_sh[t + 256] = w_enc[t + 256];
    __syncthreads();
    int warp = t >> 5, lane = t & 31;
    int row = blockIdx.x * 8 + warp;
    float acc = 0.f;
    const float4* rp = (const float4*)(inputs + (size_t)row * Dd);
#pragma unroll
    for (int k = 0; k < 4; k++) {
        float4 v = rp[lane + 32 * k];
        const float* ws = &w_sh[(lane + 32 * k) * 4];
        acc += v.x * ws[0] + v.y * ws[1] + v.z * ws[2] + v.w * ws[3];
    }
#pragma unroll
    for (int o = 16; o; o >>= 1) acc += __shfl_xor_sync(0xFFFFFFFFu, acc, o);
    if (lane == 0) {
        float val = acc + b_enc[0];
        a1_out[row] = 1.0f / (1.0f + expf(-val));
        unsigned u = __float_as_uint(val);
        u = (u & 0x80000000u) ? ~u : (u | 0x80000000u);
        keys[warp] = ((unsigned long long)u << 32) | (unsigned long long)(0xFFFFFFFFu - (unsigned)row);
    }
    __syncthreads();
    if (t == 0) {
        unsigned long long k = keys[0];
#pragma unroll
        for (int i = 1; i < 8; i++) k = (keys[i] > k) ? keys[i] : k;
        atomicMax(&g_key, k);          // order-independent, exact max -> deterministic
    }
}

// ---------------- K2: q partials: q = inputs[idx] @ w_q ----------------
__global__ void k_q_part(const float* __restrict__ inputs,
                         const float* __restrict__ w_q) {
    __shared__ float xs[64];
    int t = threadIdx.x;               // 128
    int d = blockIdx.x * 128 + t;
    int e0 = blockIdx.y * 64;
    int idx = decode_idx(g_key);
    const float* x = inputs + (size_t)idx * Dd;
    if (t < 64) xs[t] = x[e0 + t];
    __syncthreads();
    float acc = 0.f;
#pragma unroll 8
    for (int j = 0; j < 64; j++) acc += xs[j] * w_q[(size_t)(e0 + j) * Dd + d];
    g_gp1[blockIdx.y * Dd + d] = acc;
}

// ---------------- K3: q-reduce inline; u[h][e] = w_k[e, h*64:].q_h; c[h] ----------------
__global__ void k_u(const float* __restrict__ w_k,
                    const float* __restrict__ b_q,
                    const float* __restrict__ b_k) {
    __shared__ float qs[Dd];
    int t = threadIdx.x;               // 1024, 32 warps
    if (t < Dd) {
        float q = b_q[t];
#pragma unroll
        for (int i = 0; i < 8; i++) q += g_gp1[i * Dd + t];
        qs[t] = q;
        if (blockIdx.x == 0) g_q[t] = q;
    }
    __syncthreads();
    int warp = t >> 5, lane = t & 31;
    int e = blockIdx.x * 32 + warp;    // 16 blocks -> 512 rows
    const float4* wr = (const float4*)(w_k + (size_t)e * Dd + lane * 16);
    const float4* qp = (const float4*)(qs + lane * 16);
    float acc = 0.f;
#pragma unroll
    for (int k = 0; k < 4; k++) {
        float4 w = wr[k];
        float4 q = qp[k];
        acc += w.x * q.x + w.y * q.y + w.z * q.z + w.w * q.w;
    }
    acc += __shfl_xor_sync(0xFFFFFFFFu, acc, 1);
    acc += __shfl_xor_sync(0xFFFFFFFFu, acc, 2);
    if ((lane & 3) == 0) g_u[(lane >> 2) * Dd + e] = acc;
    if (blockIdx.x == 0 && t < 8) {
        float cc = 0.f;
        for (int j = 0; j < 64; j++) cc += b_k[t * 64 + j] * qs[t * 64 + j];
        g_c[t] = cc;
    }
}

// ---------------- K5: fused relu(x-Q) + depthwise 3x3 conv, float2 (2 channels/thread) ----------------
#define RSTR (HH * 256)    // row stride in float2 units

__device__ __forceinline__ float2 relu2(float2 v, float2 q) {
    return make_float2(fmaxf(v.x - q.x, 0.f), fmaxf(v.y - q.y, 0.f));
}

// FAST path (no wrap, pos always < Nn)
__device__ __forceinline__ void conv_fast2(
    const float2* __restrict__ in2,
    __nv_bfloat162* __restrict__ xx2,
    float2* __restrict__ is2,
    int t, int rt, int c0,
    const float* wa, const float* wb, float2 cb, float2 Qd)
{
    bool valid[RT + 2];
#pragma unroll
    for (int i = 0; i < RT + 2; i++) {
        int r = rt - 1 + i;
        valid[i] = (r >= 0 && r < HH);
    }
    const float2* bp = in2 + (ptrdiff_t)((rt - 1) * HH + (c0 - 1)) * 256 + t;
    float2* isp = is2 + (size_t)(rt * HH + c0) * 256 + t;
    __nv_bfloat162* xp = xx2 + (size_t)(rt * HH + c0) * 256 + t;

    float2 vA[RT + 2], vB[RT + 2], vC[RT + 2];
    const float2 z2 = make_float2(0.f, 0.f);
    bool cvA = (c0 - 1 >= 0);
#pragma unroll
    for (int i = 0; i < RT + 2; i++)
        vA[i] = (cvA && valid[i]) ? relu2(__ldg(bp + (ptrdiff_t)i * RSTR), Qd) : z2;
    bp += 256;
#pragma unroll
    for (int i = 0; i < RT + 2; i++)
        vB[i] = valid[i] ? relu2(__ldg(bp + (ptrdiff_t)i * RSTR), Qd) : z2;

#pragma unroll 4
    for (int cc = 0; cc < 32; cc++) {
        bool cvC = (c0 + cc + 1 < HH);
        bp += 256;
#pragma unroll
        for (int i = 0; i < RT + 2; i++)
            vC[i] = (cvC && valid[i]) ? relu2(__ldg(bp + (ptrdiff_t)i * RSTR), Qd) : z2;
#pragma unroll
        for (int k = 0; k < RT; k++) {
            float xx_x = vB[k + 1].x + cb.x
                       + wa[0] * vA[k].x     + wa[1] * vB[k].x     + wa[2] * vC[k].x
                       + wa[3] * vA[k + 1].x + wa[4] * vB[k + 1].x + wa[5] * vC[k + 1].x
                       + wa[6] * vA[k + 2].x + wa[7] * vB[k + 2].x + wa[8] * vC[k + 2].x;
            float xx_y = vB[k + 1].y + cb.y
                       + wb[0] * vA[k].y     + wb[1] * vB[k].y     + wb[2] * vC[k].y
                       + wb[3] * vA[k + 1].y + wb[4] * vB[k + 1].y + wb[5] * vC[k + 1].y
                       + wb[6] * vA[k + 2].y + wb[7] * vB[k + 2].y + wb[8] * vC[k + 2].y;
            isp[(ptrdiff_t)k * RSTR] = vB[k + 1];
            xp[(ptrdiff_t)k * RSTR] = __floats2bfloat162_rn(xx_x, xx_y);
        }
        isp += 256; xp += 256;
#pragma unroll
        for (int i = 0; i < RT + 2; i++) { vA[i] = vB[i]; vB[i] = vC[i]; }
    }
}

// SLOW path (wrap blocks only: bottom row tile, cols >= 220)
__device__ __forceinline__ void conv_wrap2(
    const float2* __restrict__ in2,
    __nv_bfloat162* __restrict__ xx2,
    float2* __restrict__ is2,
    int t, int rt, int c0,
    const float* wa, const float* wb, float2 cb, float2 Qd)
{
    int off[RT + 2];
    bool valid[RT + 2];
#pragma unroll
    for (int i = 0; i < RT + 2; i++) {
        int r = rt - 1 + i;
        valid[i] = (r >= 0 && r < HH);
        off[i] = (r * HH + (c0 - 1)) * 256 + t;
    }
    const float2 z2 = make_float2(0.f, 0.f);
    float2 vA[RT + 2], vB[RT + 2], vC[RT + 2];
    bool cvA = (c0 - 1 >= 0);
#pragma unroll
    for (int i = 0; i < RT + 2; i++) {
        vA[i] = (cvA && valid[i]) ? relu2(__ldg(in2 + off[i]), Qd) : z2;
        off[i] += 256;
    }
#pragma unroll
    for (int i = 0; i < RT + 2; i++)
        vB[i] = valid[i] ? relu2(__ldg(in2 + off[i]), Qd) : z2;

    for (int cc = 0; cc < 32; cc++) {
        int c = c0 + cc;
        int cn = c + 1;
        bool cvC = (cn < HH);
#pragma unroll
        for (int i = 0; i < RT + 2; i++) {
            off[i] += 256;
            int o = off[i];
            if (rt - 1 + i == HH - 1 && cn >= 220) o -= Nn * 256;
            vC[i] = (cvC && valid[i]) ? relu2(__ldg(in2 + o), Qd) : z2;
        }
        int pos0 = rt * HH + c;
#pragma unroll
        for (int k = 0; k < RT; k++) {
            float xx_x = vB[k + 1].x + cb.x
                       + wa[0] * vA[k].x     + wa[1] * vB[k].x     + wa[2] * vC[k].x
                       + wa[3] * vA[k + 1].x + wa[4] * vB[k + 1].x + wa[5] * vC[k + 1].x
                       + wa[6] * vA[k + 2].x + wa[7] * vB[k + 2].x + wa[8] * vC[k + 2].x;
            float xx_y = vB[k + 1].y + cb.y
                       + wb[0] * vA[k].y     + wb[1] * vB[k].y     + wb[2] * vC[k].y
                       + wb[3] * vA[k + 1].y + wb[4] * vB[k + 1].y + wb[5] * vC[k + 1].y
                       + wb[6] * vA[k + 2].y + wb[7] * vB[k + 2].y + wb[8] * vC[k + 2].y;
            int pos = pos0 + k * HH;
            if (pos < Nn) is2[(size_t)pos * 256 + t] = vB[k + 1];
            xx2[(size_t)pos * 256 + t] = __floats2bfloat162_rn(xx_x, xx_y);
        }
#pragma unroll
        for (int i = 0; i < RT + 2; i++) { vA[i] = vB[i]; vB[i] = vC[i]; }
    }
}

__global__ void k_conv(const float* __restrict__ inputs,
                       const float* __restrict__ conv_w,
                       const float* __restrict__ conv_b,
                       float* __restrict__ ishift) {
    int t = threadIdx.x;               // 256 threads, channel pair (2t, 2t+1)
    int d = 2 * t;
    int rt = blockIdx.y * RT;          // RT output rows per block (49 tiles * 5 = 245)
    int c0 = (blockIdx.x < 7) ? blockIdx.x * 32 : (HH - 32);
    float wa[9], wb[9];
#pragma unroll
    for (int k = 0; k < 9; k++) {
        wa[k] = conv_w[d * 9 + k];
        wb[k] = conv_w[(d + 1) * 9 + k];
    }
    float2 cb = *(const float2*)&conv_b[d];
    int idx = decode_idx(g_key);
    float2 Qd = *(const float2*)(inputs + (size_t)idx * Dd + d);

    const float2* in2 = (const float2*)inputs;
    float2* is2 = (float2*)ishift;
    __nv_bfloat162* xx2 = (__nv_bfloat162*)g_xxh;

    bool haswrap = (rt + RT >= HH) && (c0 + 32 > 220);
    if (haswrap)
        conv_wrap2(in2, xx2, is2, t, rt, c0, wa, wb, cb, Qd);
    else
        conv_fast2(in2, xx2, is2, t, rt, c0, wa, wb, cb, Qd);
}

// ---------------- K6: scores (row per warp) + fused online softmax stats ----------------
__global__ void k_scores(const float* __restrict__ cls) {
    __shared__ float4 u_sh[8 * 128];   // u as float4 per head
    __shared__ float c_sh[8];
    __shared__ float2 wred_sh[8][8];
    int t = threadIdx.x;               // 256, 8 warps
    float* uf = (float*)u_sh;
    for (int i = t; i < 4096; i += 256) uf[i] = g_u[i];
    if (t < 8) c_sh[t] = g_c[t];
    __syncthreads();
    int warp = t >> 5, lane = t & 31;
    int stride = gridDim.x * 8;
    float m_h = -1e30f, s_h = 0.f;     // valid on lanes 0-7 (head = lane)
    for (int p = blockIdx.x * 8 + warp; p < NSEQ; p += stride) {
        float4 rv[4];
        if (p == 0) {
            const float4* rp = (const float4*)cls;
#pragma unroll
            for (int k = 0; k < 4; k++) rv[k] = rp[k * 32 + lane];
        } else {
            const uint2* rp = (const uint2*)(g_xxh + (size_t)(p - 1) * Dd);
#pragma unroll
            for (int k = 0; k < 4; k++) {
                uint2 raw = rp[k * 32 + lane];
                float2 lo = __bfloat1622float2(*(const __nv_bfloat162*)&raw.x);
                float2 hi = __bfloat1622float2(*(const __nv_bfloat162*)&raw.y);
                rv[k] = make_float4(lo.x, lo.y, hi.x, hi.y);
            }
        }
        float sc[8];
#pragma unroll
        for (int h = 0; h < 8; h++) {
            float acc = 0.f;
#pragma unroll
            for (int k = 0; k < 4; k++) {
                float4 u = u_sh[h * 128 + k * 32 + lane];
                acc += rv[k].x * u.x + rv[k].y * u.y + rv[k].z * u.z + rv[k].w * u.w;
            }
            sc[h] = acc;
        }
#pragma unroll
        for (int h = 0; h < 8; h++)
#pragma unroll
            for (int o = 16; o; o >>= 1) sc[h] += __shfl_xor_sync(0xFFFFFFFFu, sc[h], o);
        if (lane < 8) {
            float s = (sc[lane] + c_sh[lane]) * INV_SQRT_D;
            g_scores[lane * SST + p] = s;
            float mn = fmaxf(m_h, s);
            s_h = s_h * expf(m_h - mn) + expf(s - mn);
            m_h = mn;
        }
    }
    if (lane < 8) wred_sh[warp][lane] = make_float2(m_h, s_h);
    __syncthreads();
    if (t < 8) {                        // t = head
        float m = -1e30f, s = 0.f;
#pragma unroll
        for (int w8 = 0; w8 < 8; w8++) {
            float2 v = wred_sh[w8][t];
            float mn = fmaxf(m, v.x);
            s = s * expf(m - mn) + v.y * expf(v.x - mn);
            m = mn;
        }
        g_mp[blockIdx.x * 8 + t] = m;
        g_sp[blockIdx.x * 8 + t] = s;
    }
}

// ---------------- K6b: merge 512 per-block (m,s) per head ----------------
__global__ void k_smax2() {
    __shared__ float2 red[512];
    int h = blockIdx.x, t = threadIdx.x;   // 8 x 512
    red[t] = make_float2(g_mp[t * 8 + h], g_sp[t * 8 + h]);
    __syncthreads();
    for (int o = 256; o; o >>= 1) {
        if (t < o) {
            float2 a = red[t], b = red[t + o];
            float mn = fmaxf(a.x, b.x);
            red[t] = make_float2(mn, a.y * expf(a.x - mn) + b.y * expf(b.x - mn));
        }
        __syncthreads();
    }
    if (t == 0) { g_m[h] = red[0].x; g_rinv[h] = 1.0f / red[0].y; }
}

// ---------------- K7: s[h][e] partials = sum_p attn[h,p]*xseq[p,e] ----------------
__global__ void k_wsum(const float* __restrict__ cls) {
    int b = blockIdx.x, t = threadIdx.x;   // NBLK7 x 128 (4 channels each)
    int p0 = b * CHUNK7;
    int p1 = min(NSEQ, p0 + CHUNK7);
    __shared__ float wsh[CHUNK7 * 8];
    __shared__ float mh[8], rh[8];
    if (t < 8) { mh[t] = g_m[t]; rh[t] = g_rinv[t]; }
    __syncthreads();
    for (int i = t; i < (p1 - p0) * 8; i += 128) {
        int pp = i >> 3, h = i & 7;
        wsh[i] = expf(g_scores[h * SST + p0 + pp] - mh[h]) * rh[h];
    }
    __syncthreads();
    float acc[8][4];
#pragma unroll
    for (int h = 0; h < 8; h++) { acc[h][0] = acc[h][1] = acc[h][2] = acc[h][3] = 0.f; }
#pragma unroll 2
    for (int p = p0; p < p1; p++) {
        float4 v;
        if (p == 0) {
            v = ((const float4*)cls)[t];
        } else {
            uint2 raw = ((const uint2*)(g_xxh + (size_t)(p - 1) * Dd))[t];
            float2 lo = __bfloat1622float2(*(const __nv_bfloat162*)&raw.x);
            float2 hi = __bfloat1622float2(*(const __nv_bfloat162*)&raw.y);
            v = make_float4(lo.x, lo.y, hi.x, hi.y);
        }
        const float* wp = &wsh[(p - p0) * 8];
#pragma unroll
        for (int h = 0; h < 8; h++) {
            float w = wp[h];
            acc[h][0] += w * v.x; acc[h][1] += w * v.y;
            acc[h][2] += w * v.z; acc[h][3] += w * v.w;
        }
    }
    float* outp = g_spart + (size_t)b * 4096;
#pragma unroll
    for (int h = 0; h < 8; h++)
        ((float4*)(outp + h * Dd))[t] = make_float4(acc[h][0], acc[h][1], acc[h][2], acc[h][3]);
}

// ---------------- K8: av partials (wred fused): gp1[by, d] ----------------
__global__ void k_av(const float* __restrict__ w_v) {
    __shared__ float xs[64];
    __shared__ float pred[4][64];
    int h = blockIdx.x, t = threadIdx.x;   // (8,8) x 256
    int e0 = blockIdx.y * 64;
    int j = t & 63, cq = t >> 6;
    float v = 0.f;
#pragma unroll 4
    for (int b = cq; b < NBLK7; b += 4)
        v += g_spart[(size_t)b * 4096 + h * Dd + e0 + j];
    pred[cq][j] = v;
    __syncthreads();
    if (t < 64) xs[t] = pred[0][t] + pred[1][t] + pred[2][t] + pred[3][t];
    __syncthreads();
    float acc = 0.f;
#pragma unroll
    for (int jj = 0; jj < 16; jj++) {
        int e = cq * 16 + jj;
        acc += xs[e] * w_v[(size_t)(e0 + e) * Dd + h * 64 + j];
    }
    pred[cq][j] = acc;
    __syncthreads();
    if (t < 64)
        g_gp1[blockIdx.y * Dd + h * 64 + t] = pred[0][t] + pred[1][t] + pred[2][t] + pred[3][t];
}

// ---------------- K9: O partials for w_o (O recomputed from gp1) ----------------
__global__ void k_o_part(const float* __restrict__ w_o,
                         const float* __restrict__ b_v) {
    __shared__ float xs[64];
    int t = threadIdx.x;               // (4,8) x 128
    int d = blockIdx.x * 128 + t;
    int e0 = blockIdx.y * 64;
    if (t < 64) {
        int e = e0 + t;
        float o = g_q[e] + b_v[e];
#pragma unroll
        for (int i = 0; i < 8; i++) o += g_gp1[i * Dd + e];
        xs[t] = o;
    }
    __syncthreads();
    float acc = 0.f;
#pragma unroll 8
    for (int jj = 0; jj < 64; jj++) acc += xs[jj] * w_o[(size_t)(e0 + jj) * Dd + d];
    g_gp2[blockIdx.y * Dd + d] = acc;
}

// ---------------- K10: O2 = O + relu(.) ; out = O2@w_fc + b_fc ; reset g_key ----------------
__global__ void k_o_fc(const float* __restrict__ b_v,
                       const float* __restrict__ b_o,
                       const float* __restrict__ w_fc,
                       const float* __restrict__ b_fc,
                       float* __restrict__ out) {
    __shared__ float r0[Dd], r1[Dd];
    int t = threadIdx.x;               // 512
    float O = g_q[t] + b_v[t];
#pragma unroll
    for (int i = 0; i < 8; i++) O += g_gp1[i * Dd + t];
    float a = b_o[t];
#pragma unroll
    for (int i = 0; i < 8; i++) a += g_gp2[i * Dd + t];
    float v = O + fmaxf(a, 0.f);
    r0[t] = v * w_fc[t * 2 + 0];
    r1[t] = v * w_fc[t * 2 + 1];
    __syncthreads();
    for (int o = 256; o; o >>= 1) {
        if (t < o) { r0[t] += r0[t + o]; r1[t] += r1[t + o]; }
        __syncthreads();
    }
    if (t == 0) {
        out[0] = r0[0] + b_fc[0];
        out[1] = r1[0] + b_fc[1];
        g_key = 0ull;                  // reset for next graph replay
    }
}

// ---------------- launch ----------------
extern "C" void kernel_launch(void* const* d_in, const int* in_sizes, int n_in,
                              void* d_out, int out_size) {
    const float* inputs = (const float*)d_in[0];
    const float* w_enc  = (const float*)d_in[1];
    const float* b_enc  = (const float*)d_in[2];
    const float* cls    = (const float*)d_in[3];
    const float* conv_w = (const float*)d_in[4];
    const float* conv_b = (const float*)d_in[5];
    const float* w_q    = (const float*)d_in[6];
    const float* b_q    = (const float*)d_in[7];
    const float* w_k    = (const float*)d_in[8];
    const float* b_k    = (const float*)d_in[9];
    const float* w_v    = (const float*)d_in[10];
    const float* b_v    = (const float*)d_in[11];
    const float* w_o    = (const float*)d_in[12];
    const float* b_o    = (const float*)d_in[13];
    const float* w_fc   = (const float*)d_in[14];
    const float* b_fc   = (const float*)d_in[15];

    float* out    = (float*)d_out;
    float* ishift = out + 2;                       // i_shift: [1,60000,512]
    float* A1     = out + 2 + (size_t)Nn * Dd;     // A1: [1,60000]

    // lazily created side stream + events (host objects only; no device mem)
    static cudaStream_t s2 = nullptr;
    static cudaEvent_t ev_fork = nullptr, ev_join = nullptr;
    if (!s2) {
        cudaStreamCreateWithFlags(&s2, cudaStreamNonBlocking);
        cudaEventCreateWithFlags(&ev_fork, cudaEventDisableTiming);
        cudaEventCreateWithFlags(&ev_join, cudaEventDisableTiming);
    }

    k_enc<<<NENC, 256>>>(inputs, w_enc, b_enc, A1);

    // fork: q/u pipeline on s2, conv on main stream
    cudaEventRecord(ev_fork, 0);
    cudaStreamWaitEvent(s2, ev_fork, 0);
    k_q_part<<<dim3(4, 8), 128, 0, s2>>>(inputs, w_q);
    k_u<<<16, 1024, 0, s2>>>(w_k, b_q, b_k);
    cudaEventRecord(ev_join, s2);

    k_conv<<<dim3(8, 49), 256>>>(inputs, conv_w, conv_b, ishift);

    // join before scores (needs g_u/g_c from s2 and g_xxh from conv)
    cudaStreamWaitEvent(0, ev_join, 0);
    k_scores<<<512, 256>>>(cls);
    k_smax2<<<8, 512>>>();
    k_wsum<<<NBLK7, 128>>>(cls);
    k_av<<<dim3(8, 8), 256>>>(w_v);
    k_o_part<<<dim3(4, 8), 128>>>(w_o, b_v);
    k_o_fc<<<1, 512>>>(b_v, b_o, w_fc, b_fc, out);
}

// round 14
// speedup vs baseline: 1.0203x; 1.0203x over previous
#include <cuda_runtime.h>
#include <cuda_bf16.h>
#include <math.h>

#define Nn 60000
#define Dd 512
#define HH 245
#define NPOS 60025
#define NSEQ 60026
#define SST 60032
#define RT 4
#define NBLK7 632
#define CHUNK7 95
#define NENC 7500
#define INV_SQRT_D 0.04419417382415922f

// ---------------- scratch (device globals: allocation-free) ----------------
__device__ unsigned long long g_key = 0ull;   // reset at end of k_o_fc each call
__device__ float g_q[Dd];
__device__ float g_u[8 * Dd];
__device__ float g_c[8];
__device__ __nv_bfloat16 g_xxh[(size_t)NPOS * Dd];   // ~61 MB conv output (bf16)
__device__ float g_scores[8 * SST];
__device__ float g_mp[512 * 8];
__device__ float g_sp[512 * 8];
__device__ float g_m[8];
__device__ float g_rinv[8];
__device__ float g_spart[(size_t)NBLK7 * 4096];
__device__ float g_gp1[8 * Dd];            // gemv partials (q, then av)
__device__ float g_gp2[8 * Dd];            // gemv partials (o)

__device__ __forceinline__ int decode_idx(unsigned long long key) {
    return (int)(0xFFFFFFFFu - (unsigned)(key & 0xFFFFFFFFull));
}

// ---------------- K1: a1 = sigmoid(inputs@w_enc+b), A1 out, argmax via atomicMax ----------------
__global__ void k_enc(const float* __restrict__ inputs,
                      const float* __restrict__ w_enc,
                      const float* __restrict__ b_enc,
                      float* __restrict__ a1_out) {
    __shared__ float w_sh[Dd];
    __shared__ unsigned long long keys[8];
    int t = threadIdx.x;               // 256 threads, 8 warps
    w_sh[t] = w_enc[t];
    w_sh[t + 256] = w_enc[t + 256];
    __syncthreads();
    int warp = t >> 5, lane = t & 31;
    int row = blockIdx.x * 8 + warp;
    float acc = 0.f;
    const float4* rp = (const float4*)(inputs + (size_t)row * Dd);
#pragma unroll
    for (int k = 0; k < 4; k++) {
        float4 v = rp[lane + 32 * k];
        const float* ws = &w_sh[(lane + 32 * k) * 4];
        acc += v.x * ws[0] + v.y * ws[1] + v.z * ws[2] + v.w * ws[3];
    }
#pragma unroll
    for (int o = 16; o; o >>= 1) acc += __shfl_xor_sync(0xFFFFFFFFu, acc, o);
    if (lane == 0) {
        float val = acc + b_enc[0];
        a1_out[row] = 1.0f / (1.0f + expf(-val));
        unsigned u = __float_as_uint(val);
        u = (u & 0x80000000u) ? ~u : (u | 0x80000000u);
        keys[warp] = ((unsigned long long)u << 32) | (unsigned long long)(0xFFFFFFFFu - (unsigned)row);
    }
    __syncthreads();
    if (t == 0) {
        unsigned long long k = keys[0];
#pragma unroll
        for (int i = 1; i < 8; i++) k = (keys[i] > k) ? keys[i] : k;
        atomicMax(&g_key, k);          // order-independent, exact max -> deterministic
    }
}

// ---------------- K2: q partials: q = inputs[idx] @ w_q ----------------
__global__ void k_q_part(const float* __restrict__ inputs,
                         const float* __restrict__ w_q) {
    __shared__ float xs[64];
    int t = threadIdx.x;               // 128
    int d = blockIdx.x * 128 + t;
    int e0 = blockIdx.y * 64;
    int idx = decode_idx(g_key);
    const float* x = inputs + (size_t)idx * Dd;
    if (t < 64) xs[t] = x[e0 + t];
    __syncthreads();
    float acc = 0.f;
#pragma unroll 8
    for (int j = 0; j < 64; j++) acc += xs[j] * w_q[(size_t)(e0 + j) * Dd + d];
    g_gp1[blockIdx.y * Dd + d] = acc;
}

// ---------------- K3: q-reduce inline; u[h][e] = w_k[e, h*64:].q_h; c[h] ----------------
__global__ void k_u(const float* __restrict__ w_k,
                    const float* __restrict__ b_q,
                    const float* __restrict__ b_k) {
    __shared__ float qs[Dd];
    int t = threadIdx.x;               // 1024, 32 warps
    if (t < Dd) {
        float q = b_q[t];
#pragma unroll
        for (int i = 0; i < 8; i++) q += g_gp1[i * Dd + t];
        qs[t] = q;
        if (blockIdx.x == 0) g_q[t] = q;
    }
    __syncthreads();
    int warp = t >> 5, lane = t & 31;
    int e = blockIdx.x * 32 + warp;    // 16 blocks -> 512 rows
    const float4* wr = (const float4*)(w_k + (size_t)e * Dd + lane * 16);
    const float4* qp = (const float4*)(qs + lane * 16);
    float acc = 0.f;
#pragma unroll
    for (int k = 0; k < 4; k++) {
        float4 w = wr[k];
        float4 q = qp[k];
        acc += w.x * q.x + w.y * q.y + w.z * q.z + w.w * q.w;
    }
    acc += __shfl_xor_sync(0xFFFFFFFFu, acc, 1);
    acc += __shfl_xor_sync(0xFFFFFFFFu, acc, 2);
    if ((lane & 3) == 0) g_u[(lane >> 2) * Dd + e] = acc;
    if (blockIdx.x == 0 && t < 8) {
        float cc = 0.f;
        for (int j = 0; j < 64; j++) cc += b_k[t * 64 + j] * qs[t * 64 + j];
        g_c[t] = cc;
    }
}

// ---------------- K5: fused relu(x-Q) + depthwise 3x3 conv, float2, RT=4 ----------------
#define RSTR (HH * 256)    // row stride in float2 units

__device__ __forceinline__ float2 relu2(float2 v, float2 q) {
    return make_float2(fmaxf(v.x - q.x, 0.f), fmaxf(v.y - q.y, 0.f));
}

// FAST path (no wrap, all RT output rows < HH)
__device__ __forceinline__ void conv_fast2(
    const float2* __restrict__ in2,
    __nv_bfloat162* __restrict__ xx2,
    float2* __restrict__ is2,
    int t, int rt, int c0,
    const float* wa, const float* wb, float2 cb, float2 Qd)
{
    bool valid[RT + 2];
#pragma unroll
    for (int i = 0; i < RT + 2; i++) {
        int r = rt - 1 + i;
        valid[i] = (r >= 0 && r < HH);
    }
    const float2* bp = in2 + (ptrdiff_t)((rt - 1) * HH + (c0 - 1)) * 256 + t;
    float2* isp = is2 + (size_t)(rt * HH + c0) * 256 + t;
    __nv_bfloat162* xp = xx2 + (size_t)(rt * HH + c0) * 256 + t;

    float2 vA[RT + 2], vB[RT + 2], vC[RT + 2];
    const float2 z2 = make_float2(0.f, 0.f);
    bool cvA = (c0 - 1 >= 0);
#pragma unroll
    for (int i = 0; i < RT + 2; i++)
        vA[i] = (cvA && valid[i]) ? relu2(__ldg(bp + (ptrdiff_t)i * RSTR), Qd) : z2;
    bp += 256;
#pragma unroll
    for (int i = 0; i < RT + 2; i++)
        vB[i] = valid[i] ? relu2(__ldg(bp + (ptrdiff_t)i * RSTR), Qd) : z2;

#pragma unroll 4
    for (int cc = 0; cc < 32; cc++) {
        bool cvC = (c0 + cc + 1 < HH);
        bp += 256;
#pragma unroll
        for (int i = 0; i < RT + 2; i++)
            vC[i] = (cvC && valid[i]) ? relu2(__ldg(bp + (ptrdiff_t)i * RSTR), Qd) : z2;
#pragma unroll
        for (int k = 0; k < RT; k++) {
            float xx_x = vB[k + 1].x + cb.x
                       + wa[0] * vA[k].x     + wa[1] * vB[k].x     + wa[2] * vC[k].x
                       + wa[3] * vA[k + 1].x + wa[4] * vB[k + 1].x + wa[5] * vC[k + 1].x
                       + wa[6] * vA[k + 2].x + wa[7] * vB[k + 2].x + wa[8] * vC[k + 2].x;
            float xx_y = vB[k + 1].y + cb.y
                       + wb[0] * vA[k].y     + wb[1] * vB[k].y     + wb[2] * vC[k].y
                       + wb[3] * vA[k + 1].y + wb[4] * vB[k + 1].y + wb[5] * vC[k + 1].y
                       + wb[6] * vA[k + 2].y + wb[7] * vB[k + 2].y + wb[8] * vC[k + 2].y;
            isp[(ptrdiff_t)k * RSTR] = vB[k + 1];
            xp[(ptrdiff_t)k * RSTR] = __floats2bfloat162_rn(xx_x, xx_y);
        }
        isp += 256; xp += 256;
#pragma unroll
        for (int i = 0; i < RT + 2; i++) { vA[i] = vB[i]; vB[i] = vC[i]; }
    }
}

// GUARDED path (wrap input reads and/or tail output rows)
__device__ __forceinline__ void conv_wrap2(
    const float2* __restrict__ in2,
    __nv_bfloat162* __restrict__ xx2,
    float2* __restrict__ is2,
    int t, int rt, int c0,
    const float* wa, const float* wb, float2 cb, float2 Qd)
{
    int off[RT + 2];
    bool valid[RT + 2];
#pragma unroll
    for (int i = 0; i < RT + 2; i++) {
        int r = rt - 1 + i;
        valid[i] = (r >= 0 && r < HH);
        off[i] = (r * HH + (c0 - 1)) * 256 + t;
    }
    const float2 z2 = make_float2(0.f, 0.f);
    float2 vA[RT + 2], vB[RT + 2], vC[RT + 2];
    bool cvA = (c0 - 1 >= 0);
#pragma unroll
    for (int i = 0; i < RT + 2; i++) {
        vA[i] = (cvA && valid[i]) ? relu2(__ldg(in2 + off[i]), Qd) : z2;
        off[i] += 256;
    }
#pragma unroll
    for (int i = 0; i < RT + 2; i++)
        vB[i] = valid[i] ? relu2(__ldg(in2 + off[i]), Qd) : z2;

    for (int cc = 0; cc < 32; cc++) {
        int c = c0 + cc;
        int cn = c + 1;
        bool cvC = (cn < HH);
#pragma unroll
        for (int i = 0; i < RT + 2; i++) {
            off[i] += 256;
            int o = off[i];
            if (rt - 1 + i == HH - 1 && cn >= 220) o -= Nn * 256;
            vC[i] = (cvC && valid[i]) ? relu2(__ldg(in2 + o), Qd) : z2;
        }
        int pos0 = rt * HH + c;
#pragma unroll
        for (int k = 0; k < RT; k++) {
            if (rt + k >= HH) break;    // tail guard: no output rows beyond HH-1
            float xx_x = vB[k + 1].x + cb.x
                       + wa[0] * vA[k].x     + wa[1] * vB[k].x     + wa[2] * vC[k].x
                       + wa[3] * vA[k + 1].x + wa[4] * vB[k + 1].x + wa[5] * vC[k + 1].x
                       + wa[6] * vA[k + 2].x + wa[7] * vB[k + 2].x + wa[8] * vC[k + 2].x;
            float xx_y = vB[k + 1].y + cb.y
                       + wb[0] * vA[k].y     + wb[1] * vB[k].y     + wb[2] * vC[k].y
                       + wb[3] * vA[k + 1].y + wb[4] * vB[k + 1].y + wb[5] * vC[k + 1].y
                       + wb[6] * vA[k + 2].y + wb[7] * vB[k + 2].y + wb[8] * vC[k + 2].y;
            int pos = pos0 + k * HH;
            if (pos < Nn) is2[(size_t)pos * 256 + t] = vB[k + 1];
            if (pos < NPOS) xx2[(size_t)pos * 256 + t] = __floats2bfloat162_rn(xx_x, xx_y);
        }
#pragma unroll
        for (int i = 0; i < RT + 2; i++) { vA[i] = vB[i]; vB[i] = vC[i]; }
    }
}

__global__ void k_conv(const float* __restrict__ inputs,
                       const float* __restrict__ conv_w,
                       const float* __restrict__ conv_b,
                       float* __restrict__ ishift) {
    int t = threadIdx.x;               // 256 threads, channel pair (2t, 2t+1)
    int d = 2 * t;
    int rt = blockIdx.y * RT;          // 62 tiles * 4 = 248 (tail guarded)
    int c0 = (blockIdx.x < 7) ? blockIdx.x * 32 : (HH - 32);
    float wa[9], wb[9];
#pragma unroll
    for (int k = 0; k < 9; k++) {
        wa[k] = conv_w[d * 9 + k];
        wb[k] = conv_w[(d + 1) * 9 + k];
    }
    float2 cb = *(const float2*)&conv_b[d];
    int idx = decode_idx(g_key);
    float2 Qd = *(const float2*)(inputs + (size_t)idx * Dd + d);

    const float2* in2 = (const float2*)inputs;
    float2* is2 = (float2*)ishift;
    __nv_bfloat162* xx2 = (__nv_bfloat162*)g_xxh;

    // wrap: bottom halo row (rt+RT) reaches row HH-1 with wrapped cols; tail: rows >= HH
    bool guarded = ((rt + RT >= HH - 1) && (c0 + 32 > 220)) || (rt + RT > HH);
    if (guarded)
        conv_wrap2(in2, xx2, is2, t, rt, c0, wa, wb, cb, Qd);
    else
        conv_fast2(in2, xx2, is2, t, rt, c0, wa, wb, cb, Qd);
}

// ---------------- K6: scores (row per warp) + fused online softmax stats ----------------
__global__ void k_scores(const float* __restrict__ cls) {
    __shared__ float4 u_sh[8 * 128];   // u as float4 per head
    __shared__ float c_sh[8];
    __shared__ float2 wred_sh[8][8];
    int t = threadIdx.x;               // 256, 8 warps
    float* uf = (float*)u_sh;
    for (int i = t; i < 4096; i += 256) uf[i] = g_u[i];
    if (t < 8) c_sh[t] = g_c[t];
    __syncthreads();
    int warp = t >> 5, lane = t & 31;
    int stride = gridDim.x * 8;
    float m_h = -1e30f, s_h = 0.f;     // valid on lanes 0-7 (head = lane)
    for (int p = blockIdx.x * 8 + warp; p < NSEQ; p += stride) {
        float4 rv[4];
        if (p == 0) {
            const float4* rp = (const float4*)cls;
#pragma unroll
            for (int k = 0; k < 4; k++) rv[k] = rp[k * 32 + lane];
        } else {
            const uint2* rp = (const uint2*)(g_xxh + (size_t)(p - 1) * Dd);
#pragma unroll
            for (int k = 0; k < 4; k++) {
                uint2 raw = rp[k * 32 + lane];
                float2 lo = __bfloat1622float2(*(const __nv_bfloat162*)&raw.x);
                float2 hi = __bfloat1622float2(*(const __nv_bfloat162*)&raw.y);
                rv[k] = make_float4(lo.x, lo.y, hi.x, hi.y);
            }
        }
        float sc[8];
#pragma unroll
        for (int h = 0; h < 8; h++) {
            float acc = 0.f;
#pragma unroll
            for (int k = 0; k < 4; k++) {
                float4 u = u_sh[h * 128 + k * 32 + lane];
                acc += rv[k].x * u.x + rv[k].y * u.y + rv[k].z * u.z + rv[k].w * u.w;
            }
            sc[h] = acc;
        }
#pragma unroll
        for (int h = 0; h < 8; h++)
#pragma unroll
            for (int o = 16; o; o >>= 1) sc[h] += __shfl_xor_sync(0xFFFFFFFFu, sc[h], o);
        if (lane < 8) {
            float s = (sc[lane] + c_sh[lane]) * INV_SQRT_D;
            g_scores[lane * SST + p] = s;
            float mn = fmaxf(m_h, s);
            s_h = s_h * expf(m_h - mn) + expf(s - mn);
            m_h = mn;
        }
    }
    if (lane < 8) wred_sh[warp][lane] = make_float2(m_h, s_h);
    __syncthreads();
    if (t < 8) {                        // t = head
        float m = -1e30f, s = 0.f;
#pragma unroll
        for (int w8 = 0; w8 < 8; w8++) {
            float2 v = wred_sh[w8][t];
            float mn = fmaxf(m, v.x);
            s = s * expf(m - mn) + v.y * expf(v.x - mn);
            m = mn;
        }
        g_mp[blockIdx.x * 8 + t] = m;
        g_sp[blockIdx.x * 8 + t] = s;
    }
}

// ---------------- K6b: merge 512 per-block (m,s) per head ----------------
__global__ void k_smax2() {
    __shared__ float2 red[512];
    int h = blockIdx.x, t = threadIdx.x;   // 8 x 512
    red[t] = make_float2(g_mp[t * 8 + h], g_sp[t * 8 + h]);
    __syncthreads();
    for (int o = 256; o; o >>= 1) {
        if (t < o) {
            float2 a = red[t], b = red[t + o];
            float mn = fmaxf(a.x, b.x);
            red[t] = make_float2(mn, a.y * expf(a.x - mn) + b.y * expf(b.x - mn));
        }
        __syncthreads();
    }
    if (t == 0) { g_m[h] = red[0].x; g_rinv[h] = 1.0f / red[0].y; }
}

// ---------------- K7: s[h][e] partials = sum_p attn[h,p]*xseq[p,e] ----------------
__global__ void k_wsum(const float* __restrict__ cls) {
    int b = blockIdx.x, t = threadIdx.x;   // NBLK7 x 128 (4 channels each)
    int p0 = b * CHUNK7;
    int p1 = min(NSEQ, p0 + CHUNK7);
    __shared__ float wsh[CHUNK7 * 8];
    __shared__ float mh[8], rh[8];
    if (t < 8) { mh[t] = g_m[t]; rh[t] = g_rinv[t]; }
    __syncthreads();
    for (int i = t; i < (p1 - p0) * 8; i += 128) {
        int pp = i >> 3, h = i & 7;
        wsh[i] = expf(g_scores[h * SST + p0 + pp] - mh[h]) * rh[h];
    }
    __syncthreads();
    float acc[8][4];
#pragma unroll
    for (int h = 0; h < 8; h++) { acc[h][0] = acc[h][1] = acc[h][2] = acc[h][3] = 0.f; }
#pragma unroll 2
    for (int p = p0; p < p1; p++) {
        float4 v;
        if (p == 0) {
            v = ((const float4*)cls)[t];
        } else {
            uint2 raw = ((const uint2*)(g_xxh + (size_t)(p - 1) * Dd))[t];
            float2 lo = __bfloat1622float2(*(const __nv_bfloat162*)&raw.x);
            float2 hi = __bfloat1622float2(*(const __nv_bfloat162*)&raw.y);
            v = make_float4(lo.x, lo.y, hi.x, hi.y);
        }
        const float* wp = &wsh[(p - p0) * 8];
#pragma unroll
        for (int h = 0; h < 8; h++) {
            float w = wp[h];
            acc[h][0] += w * v.x; acc[h][1] += w * v.y;
            acc[h][2] += w * v.z; acc[h][3] += w * v.w;
        }
    }
    float* outp = g_spart + (size_t)b * 4096;
#pragma unroll
    for (int h = 0; h < 8; h++)
        ((float4*)(outp + h * Dd))[t] = make_float4(acc[h][0], acc[h][1], acc[h][2], acc[h][3]);
}

// ---------------- K8: av partials (wred fused): gp1[by, d] ----------------
__global__ void k_av(const float* __restrict__ w_v) {
    __shared__ float xs[64];
    __shared__ float pred[4][64];
    int h = blockIdx.x, t = threadIdx.x;   // (8,8) x 256
    int e0 = blockIdx.y * 64;
    int j = t & 63, cq = t >> 6;
    float v = 0.f;
#pragma unroll 4
    for (int b = cq; b < NBLK7; b += 4)
        v += g_spart[(size_t)b * 4096 + h * Dd + e0 + j];
    pred[cq][j] = v;
    __syncthreads();
    if (t < 64) xs[t] = pred[0][t] + pred[1][t] + pred[2][t] + pred[3][t];
    __syncthreads();
    float acc = 0.f;
#pragma unroll
    for (int jj = 0; jj < 16; jj++) {
        int e = cq * 16 + jj;
        acc += xs[e] * w_v[(size_t)(e0 + e) * Dd + h * 64 + j];
    }
    pred[cq][j] = acc;
    __syncthreads();
    if (t < 64)
        g_gp1[blockIdx.y * Dd + h * 64 + t] = pred[0][t] + pred[1][t] + pred[2][t] + pred[3][t];
}

// ---------------- K9: O partials for w_o (O recomputed from gp1) ----------------
__global__ void k_o_part(const float* __restrict__ w_o,
                         const float* __restrict__ b_v) {
    __shared__ float xs[64];
    int t = threadIdx.x;               // (4,8) x 128
    int d = blockIdx.x * 128 + t;
    int e0 = blockIdx.y * 64;
    if (t < 64) {
        int e = e0 + t;
        float o = g_q[e] + b_v[e];
#pragma unroll
        for (int i = 0; i < 8; i++) o += g_gp1[i * Dd + e];
        xs[t] = o;
    }
    __syncthreads();
    float acc = 0.f;
#pragma unroll 8
    for (int jj = 0; jj < 64; jj++) acc += xs[jj] * w_o[(size_t)(e0 + jj) * Dd + d];
    g_gp2[blockIdx.y * Dd + d] = acc;
}

// ---------------- K10: O2 = O + relu(.) ; out = O2@w_fc + b_fc ; reset g_key ----------------
__global__ void k_o_fc(const float* __restrict__ b_v,
                       const float* __restrict__ b_o,
                       const float* __restrict__ w_fc,
                       const float* __restrict__ b_fc,
                       float* __restrict__ out) {
    __shared__ float r0[Dd], r1[Dd];
    int t = threadIdx.x;               // 512
    float O = g_q[t] + b_v[t];
#pragma unroll
    for (int i = 0; i < 8; i++) O += g_gp1[i * Dd + t];
    float a = b_o[t];
#pragma unroll
    for (int i = 0; i < 8; i++) a += g_gp2[i * Dd + t];
    float v = O + fmaxf(a, 0.f);
    r0[t] = v * w_fc[t * 2 + 0];
    r1[t] = v * w_fc[t * 2 + 1];
    __syncthreads();
    for (int o = 256; o; o >>= 1) {
        if (t < o) { r0[t] += r0[t + o]; r1[t] += r1[t + o]; }
        __syncthreads();
    }
    if (t == 0) {
        out[0] = r0[0] + b_fc[0];
        out[1] = r1[0] + b_fc[1];
        g_key = 0ull;                  // reset for next graph replay
    }
}

// ---------------- launch ----------------
extern "C" void kernel_launch(void* const* d_in, const int* in_sizes, int n_in,
                              void* d_out, int out_size) {
    const float* inputs = (const float*)d_in[0];
    const float* w_enc  = (const float*)d_in[1];
    const float* b_enc  = (const float*)d_in[2];
    const float* cls    = (const float*)d_in[3];
    const float* conv_w = (const float*)d_in[4];
    const float* conv_b = (const float*)d_in[5];
    const float* w_q    = (const float*)d_in[6];
    const float* b_q    = (const float*)d_in[7];
    const float* w_k    = (const float*)d_in[8];
    const float* b_k    = (const float*)d_in[9];
    const float* w_v    = (const float*)d_in[10];
    const float* b_v    = (const float*)d_in[11];
    const float* w_o    = (const float*)d_in[12];
    const float* b_o    = (const float*)d_in[13];
    const float* w_fc   = (const float*)d_in[14];
    const float* b_fc   = (const float*)d_in[15];

    float* out    = (float*)d_out;
    float* ishift = out + 2;                       // i_shift: [1,60000,512]
    float* A1     = out + 2 + (size_t)Nn * Dd;     // A1: [1,60000]

    // lazily created side stream + events (host objects only; no device mem)
    static cudaStream_t s2 = nullptr;
    static cudaEvent_t ev_fork = nullptr, ev_join = nullptr;
    if (!s2) {
        cudaStreamCreateWithFlags(&s2, cudaStreamNonBlocking);
        cudaEventCreateWithFlags(&ev_fork, cudaEventDisableTiming);
        cudaEventCreateWithFlags(&ev_join, cudaEventDisableTiming);
    }

    k_enc<<<NENC, 256>>>(inputs, w_enc, b_enc, A1);

    // fork: q/u pipeline on s2, conv on main stream
    cudaEventRecord(ev_fork, 0);
    cudaStreamWaitEvent(s2, ev_fork, 0);
    k_q_part<<<dim3(4, 8), 128, 0, s2>>>(inputs, w_q);
    k_u<<<16, 1024, 0, s2>>>(w_k, b_q, b_k);
    cudaEventRecord(ev_join, s2);

    k_conv<<<dim3(8, 62), 256>>>(inputs, conv_w, conv_b, ishift);

    // join before scores (needs g_u/g_c from s2 and g_xxh from conv)
    cudaStreamWaitEvent(0, ev_join, 0);
    k_scores<<<512, 256>>>(cls);
    k_smax2<<<8, 512>>>();
    k_wsum<<<NBLK7, 128>>>(cls);
    k_av<<<dim3(8, 8), 256>>>(w_v);
    k_o_part<<<dim3(4, 8), 128>>>(w_o, b_v);
    k_o_fc<<<1, 512>>>(b_v, b_o, w_fc, b_fc, out);
}